// round 16
// baseline (speedup 1.0000x reference)
#include <cuda_runtime.h>
#include <cuda_fp16.h>
#include <cstdint>
#include <math.h>

// ---------------- problem constants ----------------
#define BATCH   32
#define DMODEL  1024
#define LSEQ    256
#define MROWS   (BATCH * LSEQ)     // 8192
#define NLAYERS 6
#define NHEADS  16
#define HDIM    64

// ---------------- device scratch (no allocations allowed) -------------------
__device__ __half g_Xp  [MROWS * DMODEL];
__device__ float  g_h   [MROWS * DMODEL];
__device__ __half g_t16 [MROWS * DMODEL];
__device__ __half g_qkv16[MROWS * 3 * DMODEL];
__device__ float  g_scr [MROWS * DMODEL];
__device__ __half g_a16 [MROWS * DMODEL];
__device__ __half g_hid [MROWS * 4 * DMODEL];
// transposed fp16 weights [N,K], ALL layers
__device__ __half g_We[DMODEL * DMODEL];
__device__ __half g_Wq[NLAYERS * 3 * DMODEL * DMODEL];
__device__ __half g_Wp[NLAYERS * DMODEL * DMODEL];
__device__ __half g_W1[NLAYERS * 4 * DMODEL * DMODEL];
__device__ __half g_W2[NLAYERS * 4 * DMODEL * DMODEL];
// cond path fp32
__device__ float g_te[BATCH * DMODEL];
__device__ float g_t1[BATCH * DMODEL];
__device__ float g_temb[BATCH * DMODEL];
__device__ float g_cond[BATCH * DMODEL];
__device__ float g_scond[BATCH * DMODEL];
__device__ float g_mods[NLAYERS * BATCH * 6 * DMODEL];
__device__ float g_fmods[BATCH * 2 * DMODEL];

__device__ __forceinline__ float silu_f(float x) { return x / (1.0f + __expf(-x)); }

// ---------------- PTX helpers (base PTX only) --------------------------------
__device__ __forceinline__ uint32_t smem_u32(const void* p) {
    uint32_t a;
    asm("{ .reg .u64 t; cvta.to.shared.u64 t, %1; cvt.u32.u64 %0, t; }" : "=r"(a) : "l"(p));
    return a;
}
#define CP_COMMIT() asm volatile("cp.async.commit_group;" ::: "memory")
#define CP_WAIT(n)  asm volatile("cp.async.wait_group %0;" :: "n"(n) : "memory")
__device__ __forceinline__ void cp16(uint32_t dst, const void* src) {
    asm volatile("cp.async.cg.shared.global [%0], [%1], 16;" :: "r"(dst), "l"(src));
}
#define LDSM4(r, addr) \
    asm volatile("ldmatrix.sync.aligned.m8n8.x4.shared.b16 {%0,%1,%2,%3}, [%4];" \
        : "=r"((r)[0]), "=r"((r)[1]), "=r"((r)[2]), "=r"((r)[3]) : "r"(addr))
#define LDSM4T(r, addr) \
    asm volatile("ldmatrix.sync.aligned.m8n8.x4.trans.shared.b16 {%0,%1,%2,%3}, [%4];" \
        : "=r"((r)[0]), "=r"((r)[1]), "=r"((r)[2]), "=r"((r)[3]) : "r"(addr))
#define MMA_F16(d, a, b0, b1) \
    asm volatile("mma.sync.aligned.m16n8k16.row.col.f32.f16.f16.f32 " \
        "{%0,%1,%2,%3}, {%4,%5,%6,%7}, {%8,%9}, {%0,%1,%2,%3};" \
        : "+f"((d)[0]), "+f"((d)[1]), "+f"((d)[2]), "+f"((d)[3]) \
        : "r"((a)[0]), "r"((a)[1]), "r"((a)[2]), "r"((a)[3]), "r"(b0), "r"(b1))

__device__ __forceinline__ void store4_h(__half* __restrict__ H, size_t idx,
                                         float v0, float v1, float v2, float v3) {
    *(__half2*)(H + idx) = __floats2half2_rn(v0, v1);
    *(__half2*)(H + idx + 2) = __floats2half2_rn(v2, v3);
}

// ---------------- smem tile swizzle -----------------------------------------
// tile rows of 64 fp16 = 128B = 8 x 16B units; phys unit = u ^ (r&7).
__device__ __forceinline__ uint32_t swz64(int r, int u) {
    return (uint32_t)(r * 128 + ((u ^ (r & 7)) << 4));
}

// ---------------- fp16 GEMM, 128x64 tile, K-chunk 64, 2-stage, 4 CTAs/SM -----
// MODE 0: Cf = acc+bias   MODE 1: C16 = half(silu(acc+bias))
// MODE 2: Cf = res + gate[row>>8]*(acc+bias)   MODE 3: C16 = half(acc+bias)
#define S_A  0u
#define S_B  16384u
#define STG  24576u
#define GEMM_SMEM (2 * 24576)    // 48KB -> 4 CTAs/SM (192KB)

template <int MODE>
__global__ void __launch_bounds__(256, 4)
gemm_mma(const __half* __restrict__ A, const __half* __restrict__ B,
         const float* __restrict__ bias, float* __restrict__ Cf,
         __half* __restrict__ C16,
         const float* __restrict__ res, const float* __restrict__ gate, int gstride,
         int N, int K) {
    extern __shared__ __align__(128) char smem[];
    const uint32_t sb = smem_u32(smem);
    const int tid = threadIdx.x;
    const int w = tid >> 5, lane = tid & 31;
    const int wm = w & 3, wn = w >> 2;            // 4x2 warp grid; warp tile 32x32
    const int row_base = blockIdx.y * 128;
    const int col_base = blockIdx.x * 64;

    float acc[2][4][4];
#pragma unroll
    for (int i = 0; i < 2; i++)
#pragma unroll
        for (int j = 0; j < 4; j++)
#pragma unroll
            for (int q = 0; q < 4; q++) acc[i][j][q] = 0.0f;

    const int nc = K / 64;
#define LOAD_STAGE(st_, k0_) do {                                             \
        _Pragma("unroll")                                                     \
        for (int ii = 0; ii < 4; ii++) {                                      \
            int i = tid + ii * 256;                                           \
            int r = i >> 3, u = i & 7;                                        \
            cp16((st_) + S_A + swz64(r, u),                                   \
                 A + (size_t)(row_base + r) * K + (k0_) + u * 8);             \
        }                                                                     \
        _Pragma("unroll")                                                     \
        for (int ii = 0; ii < 2; ii++) {                                      \
            int i = tid + ii * 256;                                           \
            int r = i >> 3, u = i & 7;                                        \
            cp16((st_) + S_B + swz64(r, u),                                   \
                 B + (size_t)(col_base + r) * K + (k0_) + u * 8);             \
        }                                                                     \
    } while (0)

    // prologue: chunk 0 into stage 0
    LOAD_STAGE(sb, 0);
    CP_COMMIT();

    const int li = lane >> 3, lr = lane & 7;
    const int a_row = ((li & 1) << 3) + lr;
    const int a_us  = li >> 1;
    const int b_row = ((li >> 1) << 3) + lr;
    const int b_us  = li & 1;

    int stage = 0;
    for (int c = 0; c < nc; c++) {
        CP_WAIT(0);            // chunk c resident (only pending group)
        __syncthreads();       // publish; also: all warps done computing chunk c-1
        // prefetch c+1 into the other stage (holds c-1; provably drained)
        if (c + 1 < nc) {
            LOAD_STAGE(sb + (uint32_t)(stage ^ 1) * STG, (c + 1) * 64);
            CP_COMMIT();
        }

        const uint32_t st = sb + (uint32_t)stage * STG;
#pragma unroll
        for (int kk = 0; kk < 4; kk++) {
            uint32_t af[2][4], bf[2][4];
#pragma unroll
            for (int mt = 0; mt < 2; mt++)
                LDSM4(af[mt], st + S_A + swz64(wm * 32 + mt * 16 + a_row, kk * 2 + a_us));
#pragma unroll
            for (int p = 0; p < 2; p++)
                LDSM4(bf[p], st + S_B + swz64(wn * 32 + p * 16 + b_row, kk * 2 + b_us));
#pragma unroll
            for (int mt = 0; mt < 2; mt++) {
#pragma unroll
                for (int nt = 0; nt < 4; nt++) {
                    const uint32_t* fb = &bf[nt >> 1][(nt & 1) * 2];
                    MMA_F16(acc[mt][nt], af[mt], fb[0], fb[1]);
                }
            }
        }
        stage ^= 1;
    }
#undef LOAD_STAGE

    // epilogue
#pragma unroll
    for (int mt = 0; mt < 2; mt++) {
        const int r0 = row_base + wm * 32 + mt * 16 + (lane >> 2);
#pragma unroll
        for (int rr = 0; rr < 2; rr++) {
            const int row = r0 + rr * 8;
            const int bidx = row >> 8;
#pragma unroll
            for (int nt = 0; nt < 4; nt++) {
                const int col = col_base + wn * 32 + nt * 8 + (lane & 3) * 2;
                float v0 = acc[mt][nt][rr * 2 + 0] + bias[col];
                float v1 = acc[mt][nt][rr * 2 + 1] + bias[col + 1];
                if (MODE == 1 || MODE == 3) {
                    if (MODE == 1) { v0 = silu_f(v0); v1 = silu_f(v1); }
                    *(__half2*)&C16[(size_t)row * N + col] = __floats2half2_rn(v0, v1);
                } else {
                    if (MODE == 2) {
                        float2 g = *(const float2*)&gate[(size_t)bidx * gstride + col];
                        float2 rv = *(const float2*)&res[(size_t)row * N + col];
                        v0 = rv.x + g.x * v0;
                        v1 = rv.y + g.y * v1;
                    }
                    *(float2*)&Cf[(size_t)row * N + col] = make_float2(v0, v1);
                }
            }
        }
    }
}

// ---------------- tensor-core attention --------------------------------------
#define ATTN_SMEM 98304

__global__ void __launch_bounds__(256)
attn_mma(const __half* __restrict__ qkv, __half* __restrict__ O) {
    extern __shared__ __align__(128) char smem[];
    const uint32_t sb = smem_u32(smem);
    const uint32_t Qs = sb, Ks = sb + 32768u, Vs = sb + 65536u;
    const int bh = blockIdx.x;
    const int b = bh >> 4, hh = bh & 15;
    const int tid = threadIdx.x, w = tid >> 5, lane = tid & 31;
    const __half* base = qkv + (size_t)b * LSEQ * 3072 + hh * 64;

    for (int i = tid; i < 2048; i += 256) {
        int r = i >> 3, u = i & 7;
        const __half* src = base + (size_t)r * 3072 + u * 8;
        cp16(Qs + swz64(r, u), src);
        cp16(Ks + swz64(r, u), src + DMODEL);
        cp16(Vs + swz64(r, u), src + 2 * DMODEL);
    }
    CP_COMMIT();
    CP_WAIT(0);
    __syncthreads();

    const int li = lane >> 3, lr = lane & 7;
    const int a_row = ((li & 1) << 3) + lr, a_us = li >> 1;
    const int b_row = ((li >> 1) << 3) + lr, b_us = li & 1;

    uint32_t aq[2][4][4];
#pragma unroll
    for (int mt = 0; mt < 2; mt++)
#pragma unroll
        for (int kt = 0; kt < 4; kt++)
            LDSM4(aq[mt][kt], Qs + swz64(w * 32 + mt * 16 + a_row, kt * 2 + a_us));

    float mstat[2][2], ssum[2][2], oacc[2][8][4];
#pragma unroll
    for (int mt = 0; mt < 2; mt++)
#pragma unroll
        for (int rh = 0; rh < 2; rh++) { mstat[mt][rh] = -1e30f; ssum[mt][rh] = 0.0f; }
#pragma unroll
    for (int mt = 0; mt < 2; mt++)
#pragma unroll
        for (int nt = 0; nt < 8; nt++)
#pragma unroll
            for (int q = 0; q < 4; q++) oacc[mt][nt][q] = 0.0f;

    for (int kb = 0; kb < 4; kb++) {
        float sacc[2][8][4];
#pragma unroll
        for (int mt = 0; mt < 2; mt++)
#pragma unroll
            for (int nt = 0; nt < 8; nt++)
#pragma unroll
                for (int q = 0; q < 4; q++) sacc[mt][nt][q] = 0.0f;

#pragma unroll
        for (int kt = 0; kt < 4; kt++) {
#pragma unroll
            for (int knp = 0; knp < 4; knp++) {
                uint32_t bfr[4];
                LDSM4(bfr, Ks + swz64(kb * 64 + knp * 16 + b_row, kt * 2 + b_us));
#pragma unroll
                for (int mt = 0; mt < 2; mt++) {
                    MMA_F16(sacc[mt][2 * knp],     aq[mt][kt], bfr[0], bfr[1]);
                    MMA_F16(sacc[mt][2 * knp + 1], aq[mt][kt], bfr[2], bfr[3]);
                }
            }
        }

        uint32_t ph[2][8][2];
#pragma unroll
        for (int mt = 0; mt < 2; mt++) {
#pragma unroll
            for (int rh = 0; rh < 2; rh++) {
                float mx = -1e30f;
#pragma unroll
                for (int nt = 0; nt < 8; nt++)
                    mx = fmaxf(mx, fmaxf(sacc[mt][nt][2 * rh], sacc[mt][nt][2 * rh + 1]));
                mx = fmaxf(mx, __shfl_xor_sync(0xffffffffu, mx, 1));
                mx = fmaxf(mx, __shfl_xor_sync(0xffffffffu, mx, 2));
                float mnew = fmaxf(mstat[mt][rh], mx * 0.125f);
                float f = __expf(mstat[mt][rh] - mnew);
                mstat[mt][rh] = mnew;
                float rsum = 0.0f;
#pragma unroll
                for (int nt = 0; nt < 8; nt++) {
                    float p0 = __expf(sacc[mt][nt][2 * rh] * 0.125f - mnew);
                    float p1 = __expf(sacc[mt][nt][2 * rh + 1] * 0.125f - mnew);
                    rsum += p0 + p1;
                    __half2 hp = __floats2half2_rn(p0, p1);
                    ph[mt][nt][rh] = *(uint32_t*)&hp;
                }
                ssum[mt][rh] = ssum[mt][rh] * f + rsum;
#pragma unroll
                for (int dnt = 0; dnt < 8; dnt++) {
                    oacc[mt][dnt][2 * rh] *= f;
                    oacc[mt][dnt][2 * rh + 1] *= f;
                }
            }
        }

#pragma unroll
        for (int kt = 0; kt < 4; kt++) {
#pragma unroll
            for (int dnp = 0; dnp < 4; dnp++) {
                uint32_t vf[4];
                LDSM4T(vf, Vs + swz64(kb * 64 + kt * 16 + a_row, dnp * 2 + a_us));
#pragma unroll
                for (int mt = 0; mt < 2; mt++) {
                    uint32_t pa[4] = {ph[mt][2 * kt][0], ph[mt][2 * kt][1],
                                      ph[mt][2 * kt + 1][0], ph[mt][2 * kt + 1][1]};
                    MMA_F16(oacc[mt][2 * dnp],     pa, vf[0], vf[1]);
                    MMA_F16(oacc[mt][2 * dnp + 1], pa, vf[2], vf[3]);
                }
            }
        }
    }

#pragma unroll
    for (int mt = 0; mt < 2; mt++) {
#pragma unroll
        for (int rh = 0; rh < 2; rh++) {
            float s = ssum[mt][rh];
            s += __shfl_xor_sync(0xffffffffu, s, 1);
            s += __shfl_xor_sync(0xffffffffu, s, 2);
            float inv = 1.0f / s;
            const int row = b * LSEQ + w * 32 + mt * 16 + (lane >> 2) + rh * 8;
#pragma unroll
            for (int dnt = 0; dnt < 8; dnt++) {
                const int col = hh * 64 + dnt * 8 + 2 * (lane & 3);
                *(__half2*)&O[(size_t)row * DMODEL + col] =
                    __floats2half2_rn(oacc[mt][dnt][2 * rh] * inv,
                                      oacc[mt][dnt][2 * rh + 1] * inv);
            }
        }
    }
}

// ---------------- weight transpose -> fp16 (batched over layers) -------------
__global__ void transpose_h(const float* __restrict__ W, __half* __restrict__ Th,
                            int K, int N) {
    const size_t lw = (size_t)blockIdx.z * K * N;
    W += lw; Th += lw;
    __shared__ float tile[32][33];
    const int kb = blockIdx.y * 32, nb = blockIdx.x * 32;
    const int tx = threadIdx.x, ty = threadIdx.y;
#pragma unroll
    for (int i = 0; i < 32; i += 8)
        tile[ty + i][tx] = W[(size_t)(kb + ty + i) * N + nb + tx];
    __syncthreads();
#pragma unroll
    for (int i = 0; i < 32; i += 8)
        Th[(size_t)(nb + ty + i) * K + kb + tx] = __float2half_rn(tile[tx][ty + i]);
}

// ---------------- patchify / unpatchify --------------------------------------
__global__ void patchify_kernel(const float* __restrict__ x, __half* __restrict__ H) {
    int o = blockIdx.x * blockDim.x + threadIdx.x;
    if (o >= MROWS * DMODEL) return;
    int d = o & 1023, l = (o >> 10) & 255, b = o >> 18;
    int c = d >> 8, ph = (d >> 4) & 15, pw = d & 15;
    int gh = l >> 4, gw = l & 15;
    H[o] = __float2half_rn(x[(((b * 4 + c) * 256 + gh * 16 + ph) << 8) + gw * 16 + pw]);
}
__global__ void unpatchify_kernel(const float* __restrict__ hf, float* __restrict__ out) {
    int o = blockIdx.x * blockDim.x + threadIdx.x;
    if (o >= MROWS * DMODEL) return;
    int W = o & 255, H = (o >> 8) & 255, c = (o >> 16) & 3, b = o >> 18;
    int gh = H >> 4, ph = H & 15, gw = W >> 4, pw = W & 15;
    out[o] = hf[((b * 256 + gh * 16 + gw) << 10) + c * 256 + ph * 16 + pw];
}

// ---------------- LayerNorm + modulate (fp16 or fp32 out) --------------------
template <int HF>
__global__ void ln_mod_kernel(const float* __restrict__ X, const float* __restrict__ s_ptr,
                              const float* __restrict__ b_ptr, int mstride,
                              float* __restrict__ Yf, __half* __restrict__ Yh) {
    const int row = blockIdx.x;
    const int b = row >> 8;
    const int tid = threadIdx.x;
    const float* xr = X + (size_t)row * DMODEL;

    float4 v = *(const float4*)&xr[tid * 4];
    float s = v.x + v.y + v.z + v.w;
    float ss = v.x * v.x + v.y * v.y + v.z * v.z + v.w * v.w;
#pragma unroll
    for (int o = 16; o > 0; o >>= 1) {
        s += __shfl_down_sync(0xffffffffu, s, o);
        ss += __shfl_down_sync(0xffffffffu, ss, o);
    }
    __shared__ float rs[8], rss[8], stats[2];
    int wid = tid >> 5, lane = tid & 31;
    if (lane == 0) { rs[wid] = s; rss[wid] = ss; }
    __syncthreads();
    if (tid == 0) {
        float S = 0.0f, SS = 0.0f;
#pragma unroll
        for (int ww = 0; ww < 8; ww++) { S += rs[ww]; SS += rss[ww]; }
        float mean = S * (1.0f / DMODEL);
        float var = SS * (1.0f / DMODEL) - mean * mean;
        stats[0] = mean;
        stats[1] = rsqrtf(var + 1e-5f);
    }
    __syncthreads();
    float mean = stats[0], rstd = stats[1];
    const float* sp = s_ptr + (size_t)b * mstride;
    const float* bp = b_ptr + (size_t)b * mstride;
    float xv[4] = {v.x, v.y, v.z, v.w};
    float ov[4];
#pragma unroll
    for (int j = 0; j < 4; j++) {
        int col = tid * 4 + j;
        ov[j] = (xv[j] - mean) * rstd * (1.0f + sp[col]) + bp[col];
    }
    size_t base = (size_t)row * DMODEL + tid * 4;
    if (HF) {
        store4_h(Yh, base, ov[0], ov[1], ov[2], ov[3]);
    } else {
        *(float4*)&Yf[base] = make_float4(ov[0], ov[1], ov[2], ov[3]);
    }
}

// ---------------- small-M GEMM (batched over layers via y) -------------------
__global__ void small_gemm(const float* __restrict__ A, const float* __restrict__ B,
                           const float* __restrict__ bias, float* __restrict__ C,
                           int N, int mode, size_t sBl, size_t sbl, size_t sCl) {
    B += (size_t)blockIdx.y * sBl;
    bias += (size_t)blockIdx.y * sbl;
    C += (size_t)blockIdx.y * sCl;
    __shared__ __align__(16) float As[32][64];
    const int tid = threadIdx.x;
    const int c = blockIdx.x * 64 + (tid & 63);
    const int rg = tid >> 6;
    float acc[8];
#pragma unroll
    for (int r = 0; r < 8; r++) acc[r] = 0.0f;
    for (int k0 = 0; k0 < DMODEL; k0 += 64) {
        {
            int i = tid * 8;
            int row = i >> 6, col = i & 63;
            *(float4*)&As[row][col] = *(const float4*)&A[(size_t)row * DMODEL + k0 + col];
            *(float4*)&As[row][col + 4] = *(const float4*)&A[(size_t)row * DMODEL + k0 + col + 4];
        }
        __syncthreads();
        for (int k = 0; k < 64; k++) {
            float bv = B[(size_t)(k0 + k) * N + c];
#pragma unroll
            for (int r = 0; r < 8; r++) acc[r] = fmaf(As[rg * 8 + r][k], bv, acc[r]);
        }
        __syncthreads();
    }
#pragma unroll
    for (int r = 0; r < 8; r++) {
        float v = acc[r] + bias[c];
        if (mode == 1) v = silu_f(v);
        C[(size_t)(rg * 8 + r) * N + c] = v;
    }
}

// ---------------- timestep embedding + cond ----------------------------------
__global__ void te_kernel(const int* __restrict__ t, float* __restrict__ te) {
    int idx = blockIdx.x * blockDim.x + threadIdx.x;
    if (idx >= BATCH * DMODEL) return;
    int b = idx >> 10, d = idx & 1023;
    int i = (d < 512) ? d : d - 512;
    float ang = powf(10000.0f, -((float)i) / 512.0f);
    float a = (float)t[b] * ang;
    te[idx] = (d < 512) ? sinf(a) : cosf(a);
}
__global__ void cond_kernel(const int* __restrict__ y, const float* __restrict__ ytab,
                            const float* __restrict__ temb, float* __restrict__ cond,
                            float* __restrict__ scond) {
    int idx = blockIdx.x * blockDim.x + threadIdx.x;
    if (idx >= BATCH * DMODEL) return;
    int b = idx >> 10, d = idx & 1023;
    float c = ytab[(size_t)y[b] * DMODEL + d] + temb[idx];
    cond[idx] = c;
    scond[idx] = silu_f(c);
}

// ---------------- launch -----------------------------------------------------
extern "C" void kernel_launch(void* const* d_in, const int* in_sizes, int n_in,
                              void* d_out, int out_size) {
    const float* x       = (const float*)d_in[0];
    const int*   y       = (const int*)d_in[1];
    const int*   t       = (const int*)d_in[2];
    const float* xw      = (const float*)d_in[3];
    const float* xb      = (const float*)d_in[4];
    const float* ytab    = (const float*)d_in[6];
    const float* t_w1    = (const float*)d_in[7];
    const float* t_b1    = (const float*)d_in[8];
    const float* t_w2    = (const float*)d_in[9];
    const float* t_b2    = (const float*)d_in[10];
    const float* qkv_w   = (const float*)d_in[11];
    const float* qkv_b   = (const float*)d_in[12];
    const float* proj_w  = (const float*)d_in[13];
    const float* proj_b  = (const float*)d_in[14];
    const float* mlp_w1  = (const float*)d_in[15];
    const float* mlp_b1  = (const float*)d_in[16];
    const float* mlp_w2  = (const float*)d_in[17];
    const float* mlp_b2  = (const float*)d_in[18];
    const float* cond_w  = (const float*)d_in[19];
    const float* cond_b  = (const float*)d_in[20];
    const float* final_w = (const float*)d_in[21];
    const float* final_b = (const float*)d_in[22];
    float* outp = (float*)d_out;

    __half *Xp, *t16, *qkv16, *a16, *hid, *We, *Wq, *Wp, *W1, *W2;
    float *h, *scr, *te, *t1, *temb, *cond, *scond, *mods, *fmods;
    cudaGetSymbolAddress((void**)&Xp, g_Xp);
    cudaGetSymbolAddress((void**)&h, g_h);
    cudaGetSymbolAddress((void**)&t16, g_t16);
    cudaGetSymbolAddress((void**)&qkv16, g_qkv16);
    cudaGetSymbolAddress((void**)&scr, g_scr);
    cudaGetSymbolAddress((void**)&a16, g_a16);
    cudaGetSymbolAddress((void**)&hid, g_hid);
    cudaGetSymbolAddress((void**)&We, g_We);
    cudaGetSymbolAddress((void**)&Wq, g_Wq);
    cudaGetSymbolAddress((void**)&Wp, g_Wp);
    cudaGetSymbolAddress((void**)&W1, g_W1);
    cudaGetSymbolAddress((void**)&W2, g_W2);
    cudaGetSymbolAddress((void**)&te, g_te);
    cudaGetSymbolAddress((void**)&t1, g_t1);
    cudaGetSymbolAddress((void**)&temb, g_temb);
    cudaGetSymbolAddress((void**)&cond, g_cond);
    cudaGetSymbolAddress((void**)&scond, g_scond);
    cudaGetSymbolAddress((void**)&mods, g_mods);
    cudaGetSymbolAddress((void**)&fmods, g_fmods);

    cudaFuncSetAttribute(attn_mma, cudaFuncAttributeMaxDynamicSharedMemorySize, ATTN_SMEM);
    cudaFuncSetAttribute(gemm_mma<0>, cudaFuncAttributeMaxDynamicSharedMemorySize, GEMM_SMEM);
    cudaFuncSetAttribute(gemm_mma<1>, cudaFuncAttributeMaxDynamicSharedMemorySize, GEMM_SMEM);
    cudaFuncSetAttribute(gemm_mma<2>, cudaFuncAttributeMaxDynamicSharedMemorySize, GEMM_SMEM);
    cudaFuncSetAttribute(gemm_mma<3>, cudaFuncAttributeMaxDynamicSharedMemorySize, GEMM_SMEM);

    const int D = DMODEL;
    dim3 tb32(32, 8);

    // order keeps a gemm_mma at the ncu capture slot (~4th kernel)
    patchify_kernel<<<(MROWS * D) / 256, 256>>>(x, Xp);                               // 0
    transpose_h<<<dim3(D / 32, D / 32, 1), tb32>>>(xw, We, D, D);                     // 1
    transpose_h<<<dim3(3 * D / 32, D / 32, NLAYERS), tb32>>>(qkv_w, Wq, D, 3 * D);    // 2
    gemm_mma<0><<<dim3(D / 64, MROWS / 128), 256, GEMM_SMEM>>>(                       // 3
        Xp, We, xb, h, nullptr, nullptr, nullptr, 0, D, D);
    transpose_h<<<dim3(D / 32, D / 32, NLAYERS), tb32>>>(proj_w, Wp, D, D);
    transpose_h<<<dim3(4 * D / 32, D / 32, NLAYERS), tb32>>>(mlp_w1, W1, D, 4 * D);
    transpose_h<<<dim3(D / 32, 4 * D / 32, NLAYERS), tb32>>>(mlp_w2, W2, 4 * D, D);

    // cond path
    te_kernel<<<(BATCH * D) / 256, 256>>>(t, te);
    small_gemm<<<dim3(D / 64, 1), 256>>>(te, t_w1, t_b1, t1, D, 1, 0, 0, 0);
    small_gemm<<<dim3(D / 64, 1), 256>>>(t1, t_w2, t_b2, temb, D, 0, 0, 0, 0);
    cond_kernel<<<(BATCH * D) / 256, 256>>>(y, ytab, temb, cond, scond);
    small_gemm<<<dim3(6 * D / 64, NLAYERS), 256>>>(
        scond, cond_w, cond_b, mods, 6 * D, 0,
        (size_t)D * 6 * D, (size_t)6 * D, (size_t)BATCH * 6 * D);

    for (int l = 0; l < NLAYERS; l++) {
        const float* modsl = mods + (size_t)l * BATCH * 6 * D;
        const __half* wq = Wq + (size_t)l * 3 * D * D;
        const __half* wp = Wp + (size_t)l * D * D;
        const __half* w1 = W1 + (size_t)l * 4 * D * D;
        const __half* w2 = W2 + (size_t)l * 4 * D * D;
        const float* qbl = qkv_b + (size_t)l * 3 * D;
        const float* pbl = proj_b + (size_t)l * D;
        const float* b1l = mlp_b1 + (size_t)l * 4 * D;
        const float* b2l = mlp_b2 + (size_t)l * D;

        // attention branch
        ln_mod_kernel<1><<<MROWS, 256>>>(h, modsl + 0, modsl + D, 6 * D, nullptr, t16);
        gemm_mma<3><<<dim3(3 * D / 64, MROWS / 128), 256, GEMM_SMEM>>>(
            t16, wq, qbl, nullptr, qkv16, nullptr, nullptr, 0, 3 * D, D);
        attn_mma<<<BATCH * NHEADS, 256, ATTN_SMEM>>>(qkv16, a16);
        gemm_mma<2><<<dim3(D / 64, MROWS / 128), 256, GEMM_SMEM>>>(
            a16, wp, pbl, h, nullptr, h, modsl + 2 * D, 6 * D, D, D);

        // mlp branch
        ln_mod_kernel<1><<<MROWS, 256>>>(h, modsl + 3 * D, modsl + 4 * D, 6 * D, nullptr, t16);
        gemm_mma<1><<<dim3(4 * D / 64, MROWS / 128), 256, GEMM_SMEM>>>(
            t16, w1, b1l, nullptr, hid, nullptr, nullptr, 0, 4 * D, D);
        gemm_mma<2><<<dim3(D / 64, MROWS / 128), 256, GEMM_SMEM>>>(
            hid, w2, b2l, h, nullptr, h, modsl + 5 * D, 6 * D, D, 4 * D);
    }

    // final modulation + unpatchify
    small_gemm<<<dim3(2 * D / 64, 1), 256>>>(cond, final_w, final_b, fmods, 2 * D, 0, 0, 0, 0);
    ln_mod_kernel<0><<<MROWS, 256>>>(h, fmods + 0, fmods + D, 2 * D, scr, nullptr);
    unpatchify_kernel<<<(MROWS * D) / 256, 256>>>(scr, outp);
}

// round 17
// speedup vs baseline: 1.0847x; 1.0847x over previous
#include <cuda_runtime.h>
#include <cuda_fp16.h>
#include <cstdint>
#include <math.h>

// ---------------- problem constants ----------------
#define BATCH   32
#define DMODEL  1024
#define LSEQ    256
#define MROWS   (BATCH * LSEQ)     // 8192
#define NLAYERS 6
#define NHEADS  16
#define HDIM    64

// ---------------- device scratch (no allocations allowed) -------------------
__device__ __half g_Xp  [MROWS * DMODEL];
__device__ float  g_h   [MROWS * DMODEL];
__device__ __half g_t16 [MROWS * DMODEL];
__device__ __half g_qkv16[MROWS * 3 * DMODEL];
__device__ __half g_a16 [MROWS * DMODEL];
__device__ __half g_hid [MROWS * 4 * DMODEL];
// transposed fp16 weights [N,K], ALL layers
__device__ __half g_We[DMODEL * DMODEL];
__device__ __half g_Wq[NLAYERS * 3 * DMODEL * DMODEL];
__device__ __half g_Wp[NLAYERS * DMODEL * DMODEL];
__device__ __half g_W1[NLAYERS * 4 * DMODEL * DMODEL];
__device__ __half g_W2[NLAYERS * 4 * DMODEL * DMODEL];
// cond path fp32
__device__ float g_te[BATCH * DMODEL];
__device__ float g_t1[BATCH * DMODEL];
__device__ float g_temb[BATCH * DMODEL];
__device__ float g_cond[BATCH * DMODEL];
__device__ float g_scond[BATCH * DMODEL];
__device__ float g_mods[NLAYERS * BATCH * 6 * DMODEL];
__device__ float g_fmods[BATCH * 2 * DMODEL];

__device__ __forceinline__ float silu_f(float x) { return x / (1.0f + __expf(-x)); }

// ---------------- PTX helpers (base PTX only) --------------------------------
__device__ __forceinline__ uint32_t smem_u32(const void* p) {
    uint32_t a;
    asm("{ .reg .u64 t; cvta.to.shared.u64 t, %1; cvt.u32.u64 %0, t; }" : "=r"(a) : "l"(p));
    return a;
}
#define CP_COMMIT() asm volatile("cp.async.commit_group;" ::: "memory")
#define CP_WAIT(n)  asm volatile("cp.async.wait_group %0;" :: "n"(n) : "memory")
__device__ __forceinline__ void cp16(uint32_t dst, const void* src) {
    asm volatile("cp.async.cg.shared.global [%0], [%1], 16;" :: "r"(dst), "l"(src));
}
#define LDSM4(r, addr) \
    asm volatile("ldmatrix.sync.aligned.m8n8.x4.shared.b16 {%0,%1,%2,%3}, [%4];" \
        : "=r"((r)[0]), "=r"((r)[1]), "=r"((r)[2]), "=r"((r)[3]) : "r"(addr))
#define LDSM4T(r, addr) \
    asm volatile("ldmatrix.sync.aligned.m8n8.x4.trans.shared.b16 {%0,%1,%2,%3}, [%4];" \
        : "=r"((r)[0]), "=r"((r)[1]), "=r"((r)[2]), "=r"((r)[3]) : "r"(addr))
#define MMA_F16(d, a, b0, b1) \
    asm volatile("mma.sync.aligned.m16n8k16.row.col.f32.f16.f16.f32 " \
        "{%0,%1,%2,%3}, {%4,%5,%6,%7}, {%8,%9}, {%0,%1,%2,%3};" \
        : "+f"((d)[0]), "+f"((d)[1]), "+f"((d)[2]), "+f"((d)[3]) \
        : "r"((a)[0]), "r"((a)[1]), "r"((a)[2]), "r"((a)[3]), "r"(b0), "r"(b1))

__device__ __forceinline__ void store4_h(__half* __restrict__ H, size_t idx,
                                         float v0, float v1, float v2, float v3) {
    *(__half2*)(H + idx) = __floats2half2_rn(v0, v1);
    *(__half2*)(H + idx + 2) = __floats2half2_rn(v2, v3);
}

// ---------------- smem tile swizzle -----------------------------------------
// tile rows of 64 fp16 = 128B = 8 x 16B units; phys unit = u ^ (r&7).
__device__ __forceinline__ uint32_t swz64(int r, int u) {
    return (uint32_t)(r * 128 + ((u ^ (r & 7)) << 4));
}

// ---------------- fp16 GEMM, 128x64 tile, K-chunk 64, 3-stage, 3 CTAs/SM -----
// (R14 config: best measured. Fragment double-buffering across kk.)
// MODE 0: Cf = acc+bias   MODE 1: C16 = half(silu(acc+bias))
// MODE 2: Cf = res + gate[row>>8]*(acc+bias)   MODE 3: C16 = half(acc+bias)
#define S_A  0u
#define S_B  16384u
#define STG  24576u
#define NSTAGE 3
#define GEMM_SMEM (NSTAGE * 24576)   // 72KB -> 3 CTAs/SM (216KB)

template <int MODE>
__global__ void __launch_bounds__(256, 3)
gemm_mma(const __half* __restrict__ A, const __half* __restrict__ B,
         const float* __restrict__ bias, float* __restrict__ Cf,
         __half* __restrict__ C16,
         const float* __restrict__ res, const float* __restrict__ gate, int gstride,
         int N, int K) {
    extern __shared__ __align__(128) char smem[];
    const uint32_t sb = smem_u32(smem);
    const int tid = threadIdx.x;
    const int w = tid >> 5, lane = tid & 31;
    const int wm = w & 3, wn = w >> 2;            // 4x2 warp grid; warp tile 32x32
    const int row_base = blockIdx.y * 128;
    const int col_base = blockIdx.x * 64;

    float acc[2][4][4];
#pragma unroll
    for (int i = 0; i < 2; i++)
#pragma unroll
        for (int j = 0; j < 4; j++)
#pragma unroll
            for (int q = 0; q < 4; q++) acc[i][j][q] = 0.0f;

    const int nc = K / 64;
#define LOAD_STAGE(st_, k0_) do {                                             \
        _Pragma("unroll")                                                     \
        for (int ii = 0; ii < 4; ii++) {                                      \
            int i = tid + ii * 256;                                           \
            int r = i >> 3, u = i & 7;                                        \
            cp16((st_) + S_A + swz64(r, u),                                   \
                 A + (size_t)(row_base + r) * K + (k0_) + u * 8);             \
        }                                                                     \
        _Pragma("unroll")                                                     \
        for (int ii = 0; ii < 2; ii++) {                                      \
            int i = tid + ii * 256;                                           \
            int r = i >> 3, u = i & 7;                                        \
            cp16((st_) + S_B + swz64(r, u),                                   \
                 B + (size_t)(col_base + r) * K + (k0_) + u * 8);             \
        }                                                                     \
    } while (0)

#pragma unroll
    for (int p = 0; p < NSTAGE - 1; p++) {
        const uint32_t st = sb + (uint32_t)p * STG;
        LOAD_STAGE(st, p * 64);
        CP_COMMIT();
    }

    const int li = lane >> 3, lr = lane & 7;
    const int a_row = ((li & 1) << 3) + lr;
    const int a_us  = li >> 1;
    const int b_row = ((li >> 1) << 3) + lr;
    const int b_us  = li & 1;
    const int arb0 = wm * 32 + a_row;
    const int brb0 = wn * 32 + b_row;

    uint32_t af[2][2][4], bf[2][2][4];   // [buf][tile][frag]

#define LOAD_FRAGS(buf, st_, kk_) do {                                        \
        const int ua = (kk_) * 2 + a_us;                                      \
        const int ub = (kk_) * 2 + b_us;                                      \
        LDSM4(af[buf][0], (st_) + S_A + swz64(arb0,      ua));                \
        LDSM4(af[buf][1], (st_) + S_A + swz64(arb0 + 16, ua));                \
        LDSM4(bf[buf][0], (st_) + S_B + swz64(brb0,      ub));                \
        LDSM4(bf[buf][1], (st_) + S_B + swz64(brb0 + 16, ub));                \
    } while (0)

#define DO_MMAS(buf) do {                                                     \
        _Pragma("unroll")                                                     \
        for (int mt = 0; mt < 2; mt++) {                                      \
            _Pragma("unroll")                                                 \
            for (int nt = 0; nt < 4; nt++) {                                  \
                const uint32_t* fb = &bf[buf][nt >> 1][(nt & 1) * 2];         \
                MMA_F16(acc[mt][nt], af[buf][mt], fb[0], fb[1]);              \
            }                                                                 \
        }                                                                     \
    } while (0)

    int stage = 0, pstage = NSTAGE - 1;
    for (int c = 0; c < nc; c++) {
        CP_WAIT(NSTAGE - 2);
        __syncthreads();

        if (c + NSTAGE - 1 < nc) {
            const uint32_t st2 = sb + (uint32_t)pstage * STG;
            LOAD_STAGE(st2, (c + NSTAGE - 1) * 64);
        }
        CP_COMMIT();

        const uint32_t st = sb + (uint32_t)stage * STG;
        LOAD_FRAGS(0, st, 0);
        LOAD_FRAGS(1, st, 1);
        DO_MMAS(0);
        LOAD_FRAGS(0, st, 2);
        DO_MMAS(1);
        LOAD_FRAGS(1, st, 3);
        DO_MMAS(0);
        DO_MMAS(1);

        stage = (stage == NSTAGE - 1) ? 0 : stage + 1;
        pstage = (pstage == NSTAGE - 1) ? 0 : pstage + 1;
    }
#undef LOAD_STAGE
#undef LOAD_FRAGS
#undef DO_MMAS

    // epilogue
#pragma unroll
    for (int mt = 0; mt < 2; mt++) {
        const int r0 = row_base + wm * 32 + mt * 16 + (lane >> 2);
#pragma unroll
        for (int rr = 0; rr < 2; rr++) {
            const int row = r0 + rr * 8;
            const int bidx = row >> 8;
#pragma unroll
            for (int nt = 0; nt < 4; nt++) {
                const int col = col_base + wn * 32 + nt * 8 + (lane & 3) * 2;
                float v0 = acc[mt][nt][rr * 2 + 0] + bias[col];
                float v1 = acc[mt][nt][rr * 2 + 1] + bias[col + 1];
                if (MODE == 1 || MODE == 3) {
                    if (MODE == 1) { v0 = silu_f(v0); v1 = silu_f(v1); }
                    *(__half2*)&C16[(size_t)row * N + col] = __floats2half2_rn(v0, v1);
                } else {
                    if (MODE == 2) {
                        float2 g = *(const float2*)&gate[(size_t)bidx * gstride + col];
                        float2 rv = *(const float2*)&res[(size_t)row * N + col];
                        v0 = rv.x + g.x * v0;
                        v1 = rv.y + g.y * v1;
                    }
                    *(float2*)&Cf[(size_t)row * N + col] = make_float2(v0, v1);
                }
            }
        }
    }
}

// ---------------- tensor-core attention --------------------------------------
#define ATTN_SMEM 98304

__global__ void __launch_bounds__(256)
attn_mma(const __half* __restrict__ qkv, __half* __restrict__ O) {
    extern __shared__ __align__(128) char smem[];
    const uint32_t sb = smem_u32(smem);
    const uint32_t Qs = sb, Ks = sb + 32768u, Vs = sb + 65536u;
    const int bh = blockIdx.x;
    const int b = bh >> 4, hh = bh & 15;
    const int tid = threadIdx.x, w = tid >> 5, lane = tid & 31;
    const __half* base = qkv + (size_t)b * LSEQ * 3072 + hh * 64;

    for (int i = tid; i < 2048; i += 256) {
        int r = i >> 3, u = i & 7;
        const __half* src = base + (size_t)r * 3072 + u * 8;
        cp16(Qs + swz64(r, u), src);
        cp16(Ks + swz64(r, u), src + DMODEL);
        cp16(Vs + swz64(r, u), src + 2 * DMODEL);
    }
    CP_COMMIT();
    CP_WAIT(0);
    __syncthreads();

    const int li = lane >> 3, lr = lane & 7;
    const int a_row = ((li & 1) << 3) + lr, a_us = li >> 1;
    const int b_row = ((li >> 1) << 3) + lr, b_us = li & 1;

    uint32_t aq[2][4][4];
#pragma unroll
    for (int mt = 0; mt < 2; mt++)
#pragma unroll
        for (int kt = 0; kt < 4; kt++)
            LDSM4(aq[mt][kt], Qs + swz64(w * 32 + mt * 16 + a_row, kt * 2 + a_us));

    float mstat[2][2], ssum[2][2], oacc[2][8][4];
#pragma unroll
    for (int mt = 0; mt < 2; mt++)
#pragma unroll
        for (int rh = 0; rh < 2; rh++) { mstat[mt][rh] = -1e30f; ssum[mt][rh] = 0.0f; }
#pragma unroll
    for (int mt = 0; mt < 2; mt++)
#pragma unroll
        for (int nt = 0; nt < 8; nt++)
#pragma unroll
            for (int q = 0; q < 4; q++) oacc[mt][nt][q] = 0.0f;

    for (int kb = 0; kb < 4; kb++) {
        float sacc[2][8][4];
#pragma unroll
        for (int mt = 0; mt < 2; mt++)
#pragma unroll
            for (int nt = 0; nt < 8; nt++)
#pragma unroll
                for (int q = 0; q < 4; q++) sacc[mt][nt][q] = 0.0f;

#pragma unroll
        for (int kt = 0; kt < 4; kt++) {
#pragma unroll
            for (int knp = 0; knp < 4; knp++) {
                uint32_t bfr[4];
                LDSM4(bfr, Ks + swz64(kb * 64 + knp * 16 + b_row, kt * 2 + b_us));
#pragma unroll
                for (int mt = 0; mt < 2; mt++) {
                    MMA_F16(sacc[mt][2 * knp],     aq[mt][kt], bfr[0], bfr[1]);
                    MMA_F16(sacc[mt][2 * knp + 1], aq[mt][kt], bfr[2], bfr[3]);
                }
            }
        }

        uint32_t ph[2][8][2];
#pragma unroll
        for (int mt = 0; mt < 2; mt++) {
#pragma unroll
            for (int rh = 0; rh < 2; rh++) {
                float mx = -1e30f;
#pragma unroll
                for (int nt = 0; nt < 8; nt++)
                    mx = fmaxf(mx, fmaxf(sacc[mt][nt][2 * rh], sacc[mt][nt][2 * rh + 1]));
                mx = fmaxf(mx, __shfl_xor_sync(0xffffffffu, mx, 1));
                mx = fmaxf(mx, __shfl_xor_sync(0xffffffffu, mx, 2));
                float mnew = fmaxf(mstat[mt][rh], mx * 0.125f);
                float f = __expf(mstat[mt][rh] - mnew);
                mstat[mt][rh] = mnew;
                float rsum = 0.0f;
#pragma unroll
                for (int nt = 0; nt < 8; nt++) {
                    float p0 = __expf(sacc[mt][nt][2 * rh] * 0.125f - mnew);
                    float p1 = __expf(sacc[mt][nt][2 * rh + 1] * 0.125f - mnew);
                    rsum += p0 + p1;
                    __half2 hp = __floats2half2_rn(p0, p1);
                    ph[mt][nt][rh] = *(uint32_t*)&hp;
                }
                ssum[mt][rh] = ssum[mt][rh] * f + rsum;
#pragma unroll
                for (int dnt = 0; dnt < 8; dnt++) {
                    oacc[mt][dnt][2 * rh] *= f;
                    oacc[mt][dnt][2 * rh + 1] *= f;
                }
            }
        }

#pragma unroll
        for (int kt = 0; kt < 4; kt++) {
#pragma unroll
            for (int dnp = 0; dnp < 4; dnp++) {
                uint32_t vf[4];
                LDSM4T(vf, Vs + swz64(kb * 64 + kt * 16 + a_row, dnp * 2 + a_us));
#pragma unroll
                for (int mt = 0; mt < 2; mt++) {
                    uint32_t pa[4] = {ph[mt][2 * kt][0], ph[mt][2 * kt][1],
                                      ph[mt][2 * kt + 1][0], ph[mt][2 * kt + 1][1]};
                    MMA_F16(oacc[mt][2 * dnp],     pa, vf[0], vf[1]);
                    MMA_F16(oacc[mt][2 * dnp + 1], pa, vf[2], vf[3]);
                }
            }
        }
    }

#pragma unroll
    for (int mt = 0; mt < 2; mt++) {
#pragma unroll
        for (int rh = 0; rh < 2; rh++) {
            float s = ssum[mt][rh];
            s += __shfl_xor_sync(0xffffffffu, s, 1);
            s += __shfl_xor_sync(0xffffffffu, s, 2);
            float inv = 1.0f / s;
            const int row = b * LSEQ + w * 32 + mt * 16 + (lane >> 2) + rh * 8;
#pragma unroll
            for (int dnt = 0; dnt < 8; dnt++) {
                const int col = hh * 64 + dnt * 8 + 2 * (lane & 3);
                *(__half2*)&O[(size_t)row * DMODEL + col] =
                    __floats2half2_rn(oacc[mt][dnt][2 * rh] * inv,
                                      oacc[mt][dnt][2 * rh + 1] * inv);
            }
        }
    }
}

// ---------------- weight transpose -> fp16 (batched over layers) -------------
__global__ void transpose_h(const float* __restrict__ W, __half* __restrict__ Th,
                            int K, int N) {
    const size_t lw = (size_t)blockIdx.z * K * N;
    W += lw; Th += lw;
    __shared__ float tile[32][33];
    const int kb = blockIdx.y * 32, nb = blockIdx.x * 32;
    const int tx = threadIdx.x, ty = threadIdx.y;
#pragma unroll
    for (int i = 0; i < 32; i += 8)
        tile[ty + i][tx] = W[(size_t)(kb + ty + i) * N + nb + tx];
    __syncthreads();
#pragma unroll
    for (int i = 0; i < 32; i += 8)
        Th[(size_t)(nb + ty + i) * K + kb + tx] = __float2half_rn(tile[tx][ty + i]);
}

// ---------------- patchify -------------------------------------------------
__global__ void patchify_kernel(const float* __restrict__ x, __half* __restrict__ H) {
    int o = blockIdx.x * blockDim.x + threadIdx.x;
    if (o >= MROWS * DMODEL) return;
    int d = o & 1023, l = (o >> 10) & 255, b = o >> 18;
    int c = d >> 8, ph = (d >> 4) & 15, pw = d & 15;
    int gh = l >> 4, gw = l & 15;
    H[o] = __float2half_rn(x[(((b * 4 + c) * 256 + gh * 16 + ph) << 8) + gw * 16 + pw]);
}

// ---------------- LayerNorm + modulate -> fp16 -------------------------------
__global__ void ln_mod_kernel(const float* __restrict__ X, const float* __restrict__ s_ptr,
                              const float* __restrict__ b_ptr, int mstride,
                              __half* __restrict__ Yh) {
    const int row = blockIdx.x;
    const int b = row >> 8;
    const int tid = threadIdx.x;
    const float* xr = X + (size_t)row * DMODEL;

    float4 v = *(const float4*)&xr[tid * 4];
    float s = v.x + v.y + v.z + v.w;
    float ss = v.x * v.x + v.y * v.y + v.z * v.z + v.w * v.w;
#pragma unroll
    for (int o = 16; o > 0; o >>= 1) {
        s += __shfl_down_sync(0xffffffffu, s, o);
        ss += __shfl_down_sync(0xffffffffu, ss, o);
    }
    __shared__ float rs[8], rss[8], stats[2];
    int wid = tid >> 5, lane = tid & 31;
    if (lane == 0) { rs[wid] = s; rss[wid] = ss; }
    __syncthreads();
    if (tid == 0) {
        float S = 0.0f, SS = 0.0f;
#pragma unroll
        for (int ww = 0; ww < 8; ww++) { S += rs[ww]; SS += rss[ww]; }
        float mean = S * (1.0f / DMODEL);
        float var = SS * (1.0f / DMODEL) - mean * mean;
        stats[0] = mean;
        stats[1] = rsqrtf(var + 1e-5f);
    }
    __syncthreads();
    float mean = stats[0], rstd = stats[1];
    const float* sp = s_ptr + (size_t)b * mstride;
    const float* bp = b_ptr + (size_t)b * mstride;
    float xv[4] = {v.x, v.y, v.z, v.w};
    float ov[4];
#pragma unroll
    for (int j = 0; j < 4; j++) {
        int col = tid * 4 + j;
        ov[j] = (xv[j] - mean) * rstd * (1.0f + sp[col]) + bp[col];
    }
    store4_h(Yh, (size_t)row * DMODEL + tid * 4, ov[0], ov[1], ov[2], ov[3]);
}

// ---------------- FUSED final LayerNorm + modulate + unpatchify --------------
// row = b*256 + l  (l = gh*16+gw); col = c*256 + ph*16 + pw
// out[b][c][gh*16+ph][gw*16+pw] = ln_mod(h[row], fmods)[col]
__global__ void ln_mod_unpatch(const float* __restrict__ X, const float* __restrict__ s_ptr,
                               const float* __restrict__ b_ptr, float* __restrict__ out) {
    const int row = blockIdx.x;
    const int b = row >> 8;
    const int l = row & 255;
    const int gh = l >> 4, gw = l & 15;
    const int tid = threadIdx.x;
    const float* xr = X + (size_t)row * DMODEL;

    float4 v = *(const float4*)&xr[tid * 4];
    float s = v.x + v.y + v.z + v.w;
    float ss = v.x * v.x + v.y * v.y + v.z * v.z + v.w * v.w;
#pragma unroll
    for (int o = 16; o > 0; o >>= 1) {
        s += __shfl_down_sync(0xffffffffu, s, o);
        ss += __shfl_down_sync(0xffffffffu, ss, o);
    }
    __shared__ float rs[8], rss[8], stats[2];
    int wid = tid >> 5, lane = tid & 31;
    if (lane == 0) { rs[wid] = s; rss[wid] = ss; }
    __syncthreads();
    if (tid == 0) {
        float S = 0.0f, SS = 0.0f;
#pragma unroll
        for (int ww = 0; ww < 8; ww++) { S += rs[ww]; SS += rss[ww]; }
        float mean = S * (1.0f / DMODEL);
        float var = SS * (1.0f / DMODEL) - mean * mean;
        stats[0] = mean;
        stats[1] = rsqrtf(var + 1e-5f);
    }
    __syncthreads();
    float mean = stats[0], rstd = stats[1];
    const float* sp = s_ptr + (size_t)b * 2 * DMODEL;
    const float* bp = b_ptr + (size_t)b * 2 * DMODEL;
    // cols tid*4 .. tid*4+3 (pw-aligned quad: pw = (col&15), col%4==0 ⇒ contiguous out)
    const int col0 = tid * 4;
    const int c = col0 >> 8, ph = (col0 >> 4) & 15, pw = col0 & 15;
    float ov[4];
    float xv[4] = {v.x, v.y, v.z, v.w};
#pragma unroll
    for (int j = 0; j < 4; j++) {
        int col = col0 + j;
        ov[j] = (xv[j] - mean) * rstd * (1.0f + sp[col]) + bp[col];
    }
    size_t oidx = (((size_t)(b * 4 + c) * 256 + gh * 16 + ph) << 8) + gw * 16 + pw;
    *(float4*)&out[oidx] = make_float4(ov[0], ov[1], ov[2], ov[3]);
}

// ---------------- small-M GEMM (batched over layers via y) -------------------
__global__ void small_gemm(const float* __restrict__ A, const float* __restrict__ B,
                           const float* __restrict__ bias, float* __restrict__ C,
                           int N, int mode, size_t sBl, size_t sbl, size_t sCl) {
    B += (size_t)blockIdx.y * sBl;
    bias += (size_t)blockIdx.y * sbl;
    C += (size_t)blockIdx.y * sCl;
    __shared__ __align__(16) float As[32][64];
    const int tid = threadIdx.x;
    const int c = blockIdx.x * 64 + (tid & 63);
    const int rg = tid >> 6;
    float acc[8];
#pragma unroll
    for (int r = 0; r < 8; r++) acc[r] = 0.0f;
    for (int k0 = 0; k0 < DMODEL; k0 += 64) {
        {
            int i = tid * 8;
            int row = i >> 6, col = i & 63;
            *(float4*)&As[row][col] = *(const float4*)&A[(size_t)row * DMODEL + k0 + col];
            *(float4*)&As[row][col + 4] = *(const float4*)&A[(size_t)row * DMODEL + k0 + col + 4];
        }
        __syncthreads();
        for (int k = 0; k < 64; k++) {
            float bv = B[(size_t)(k0 + k) * N + c];
#pragma unroll
            for (int r = 0; r < 8; r++) acc[r] = fmaf(As[rg * 8 + r][k], bv, acc[r]);
        }
        __syncthreads();
    }
#pragma unroll
    for (int r = 0; r < 8; r++) {
        float v = acc[r] + bias[c];
        if (mode == 1) v = silu_f(v);
        C[(size_t)(rg * 8 + r) * N + c] = v;
    }
}

// ---------------- timestep embedding + cond ----------------------------------
__global__ void te_kernel(const int* __restrict__ t, float* __restrict__ te) {
    int idx = blockIdx.x * blockDim.x + threadIdx.x;
    if (idx >= BATCH * DMODEL) return;
    int b = idx >> 10, d = idx & 1023;
    int i = (d < 512) ? d : d - 512;
    float ang = powf(10000.0f, -((float)i) / 512.0f);
    float a = (float)t[b] * ang;
    te[idx] = (d < 512) ? sinf(a) : cosf(a);
}
__global__ void cond_kernel(const int* __restrict__ y, const float* __restrict__ ytab,
                            const float* __restrict__ temb, float* __restrict__ cond,
                            float* __restrict__ scond) {
    int idx = blockIdx.x * blockDim.x + threadIdx.x;
    if (idx >= BATCH * DMODEL) return;
    int b = idx >> 10, d = idx & 1023;
    float c = ytab[(size_t)y[b] * DMODEL + d] + temb[idx];
    cond[idx] = c;
    scond[idx] = silu_f(c);
}

// ---------------- launch -----------------------------------------------------
extern "C" void kernel_launch(void* const* d_in, const int* in_sizes, int n_in,
                              void* d_out, int out_size) {
    const float* x       = (const float*)d_in[0];
    const int*   y       = (const int*)d_in[1];
    const int*   t       = (const int*)d_in[2];
    const float* xw      = (const float*)d_in[3];
    const float* xb      = (const float*)d_in[4];
    const float* ytab    = (const float*)d_in[6];
    const float* t_w1    = (const float*)d_in[7];
    const float* t_b1    = (const float*)d_in[8];
    const float* t_w2    = (const float*)d_in[9];
    const float* t_b2    = (const float*)d_in[10];
    const float* qkv_w   = (const float*)d_in[11];
    const float* qkv_b   = (const float*)d_in[12];
    const float* proj_w  = (const float*)d_in[13];
    const float* proj_b  = (const float*)d_in[14];
    const float* mlp_w1  = (const float*)d_in[15];
    const float* mlp_b1  = (const float*)d_in[16];
    const float* mlp_w2  = (const float*)d_in[17];
    const float* mlp_b2  = (const float*)d_in[18];
    const float* cond_w  = (const float*)d_in[19];
    const float* cond_b  = (const float*)d_in[20];
    const float* final_w = (const float*)d_in[21];
    const float* final_b = (const float*)d_in[22];
    float* outp = (float*)d_out;

    __half *Xp, *t16, *qkv16, *a16, *hid, *We, *Wq, *Wp, *W1, *W2;
    float *h, *te, *t1, *temb, *cond, *scond, *mods, *fmods;
    cudaGetSymbolAddress((void**)&Xp, g_Xp);
    cudaGetSymbolAddress((void**)&h, g_h);
    cudaGetSymbolAddress((void**)&t16, g_t16);
    cudaGetSymbolAddress((void**)&qkv16, g_qkv16);
    cudaGetSymbolAddress((void**)&a16, g_a16);
    cudaGetSymbolAddress((void**)&hid, g_hid);
    cudaGetSymbolAddress((void**)&We, g_We);
    cudaGetSymbolAddress((void**)&Wq, g_Wq);
    cudaGetSymbolAddress((void**)&Wp, g_Wp);
    cudaGetSymbolAddress((void**)&W1, g_W1);
    cudaGetSymbolAddress((void**)&W2, g_W2);
    cudaGetSymbolAddress((void**)&te, g_te);
    cudaGetSymbolAddress((void**)&t1, g_t1);
    cudaGetSymbolAddress((void**)&temb, g_temb);
    cudaGetSymbolAddress((void**)&cond, g_cond);
    cudaGetSymbolAddress((void**)&scond, g_scond);
    cudaGetSymbolAddress((void**)&mods, g_mods);
    cudaGetSymbolAddress((void**)&fmods, g_fmods);

    cudaFuncSetAttribute(attn_mma, cudaFuncAttributeMaxDynamicSharedMemorySize, ATTN_SMEM);
    cudaFuncSetAttribute(gemm_mma<0>, cudaFuncAttributeMaxDynamicSharedMemorySize, GEMM_SMEM);
    cudaFuncSetAttribute(gemm_mma<1>, cudaFuncAttributeMaxDynamicSharedMemorySize, GEMM_SMEM);
    cudaFuncSetAttribute(gemm_mma<2>, cudaFuncAttributeMaxDynamicSharedMemorySize, GEMM_SMEM);
    cudaFuncSetAttribute(gemm_mma<3>, cudaFuncAttributeMaxDynamicSharedMemorySize, GEMM_SMEM);

    const int D = DMODEL;
    dim3 tb32(32, 8);

    // order keeps a gemm_mma at the ncu capture slot (~4th kernel)
    patchify_kernel<<<(MROWS * D) / 256, 256>>>(x, Xp);                               // 0
    transpose_h<<<dim3(D / 32, D / 32, 1), tb32>>>(xw, We, D, D);                     // 1
    transpose_h<<<dim3(3 * D / 32, D / 32, NLAYERS), tb32>>>(qkv_w, Wq, D, 3 * D);    // 2
    gemm_mma<0><<<dim3(D / 64, MROWS / 128), 256, GEMM_SMEM>>>(                       // 3
        Xp, We, xb, h, nullptr, nullptr, nullptr, 0, D, D);
    transpose_h<<<dim3(D / 32, D / 32, NLAYERS), tb32>>>(proj_w, Wp, D, D);
    transpose_h<<<dim3(4 * D / 32, D / 32, NLAYERS), tb32>>>(mlp_w1, W1, D, 4 * D);
    transpose_h<<<dim3(D / 32, 4 * D / 32, NLAYERS), tb32>>>(mlp_w2, W2, 4 * D, D);

    // cond path
    te_kernel<<<(BATCH * D) / 256, 256>>>(t, te);
    small_gemm<<<dim3(D / 64, 1), 256>>>(te, t_w1, t_b1, t1, D, 1, 0, 0, 0);
    small_gemm<<<dim3(D / 64, 1), 256>>>(t1, t_w2, t_b2, temb, D, 0, 0, 0, 0);
    cond_kernel<<<(BATCH * D) / 256, 256>>>(y, ytab, temb, cond, scond);
    small_gemm<<<dim3(6 * D / 64, NLAYERS), 256>>>(
        scond, cond_w, cond_b, mods, 6 * D, 0,
        (size_t)D * 6 * D, (size_t)6 * D, (size_t)BATCH * 6 * D);

    for (int l = 0; l < NLAYERS; l++) {
        const float* modsl = mods + (size_t)l * BATCH * 6 * D;
        const __half* wq = Wq + (size_t)l * 3 * D * D;
        const __half* wp = Wp + (size_t)l * D * D;
        const __half* w1 = W1 + (size_t)l * 4 * D * D;
        const __half* w2 = W2 + (size_t)l * 4 * D * D;
        const float* qbl = qkv_b + (size_t)l * 3 * D;
        const float* pbl = proj_b + (size_t)l * D;
        const float* b1l = mlp_b1 + (size_t)l * 4 * D;
        const float* b2l = mlp_b2 + (size_t)l * D;

        // attention branch
        ln_mod_kernel<<<MROWS, 256>>>(h, modsl + 0, modsl + D, 6 * D, t16);
        gemm_mma<3><<<dim3(3 * D / 64, MROWS / 128), 256, GEMM_SMEM>>>(
            t16, wq, qbl, nullptr, qkv16, nullptr, nullptr, 0, 3 * D, D);
        attn_mma<<<BATCH * NHEADS, 256, ATTN_SMEM>>>(qkv16, a16);
        gemm_mma<2><<<dim3(D / 64, MROWS / 128), 256, GEMM_SMEM>>>(
            a16, wp, pbl, h, nullptr, h, modsl + 2 * D, 6 * D, D, D);

        // mlp branch
        ln_mod_kernel<<<MROWS, 256>>>(h, modsl + 3 * D, modsl + 4 * D, 6 * D, t16);
        gemm_mma<1><<<dim3(4 * D / 64, MROWS / 128), 256, GEMM_SMEM>>>(
            t16, w1, b1l, nullptr, hid, nullptr, nullptr, 0, 4 * D, D);
        gemm_mma<2><<<dim3(D / 64, MROWS / 128), 256, GEMM_SMEM>>>(
            hid, w2, b2l, h, nullptr, h, modsl + 5 * D, 6 * D, D, 4 * D);
    }

    // final modulation + fused ln+unpatchify
    small_gemm<<<dim3(2 * D / 64, 1), 256>>>(cond, final_w, final_b, fmods, 2 * D, 0, 0, 0, 0);
    ln_mod_unpatch<<<MROWS, 256>>>(h, fmods + 0, fmods + D, outp);
}